// round 14
// baseline (speedup 1.0000x reference)
#include <cuda_runtime.h>
#include <cuda_fp16.h>
#include <math.h>

// Problem constants (fixed shapes per reference)
#define CN 100000      // nodes
#define CE 1600000     // edges
#define CG 4096        // graphs
#define CH 128         // hidden
#define CF 32          // input features
#define NB_SCAN 98     // ceil(CN/1024)
#define ASTR 132       // float stride of smem A-tile rows (k-major)

// ---------------- device scratch (static, no allocation) ----------------
__device__ __align__(16) int   g_deg[CN];
__device__ __align__(16) int   g_rowptr[CN];
__device__ __align__(16) int   g_cursor[CN];
__device__ __align__(16) int   g_col[CE];
__device__ __align__(16) float g_dinv[CN];
__device__ __align__(16) __half g_bufA16[(size_t)CN * CH];    // fp16 agg output (GEMM A)
__device__ __align__(16) __half g_bufB16[(size_t)CN * CH];    // fp16 pre-BN hidden
__device__ __align__(16) __half g_x16[(size_t)CN * CF];       // fp16 input features
__device__ __align__(16) float g_sums[6 * CH];   // (sum, sumsq) x 3 layers
__device__ __align__(16) int   g_bsums[128];

// ---------------- packed fp32x2 helpers ----------------
__device__ __forceinline__ unsigned long long pack2(float lo, float hi) {
    unsigned long long r;
    asm("mov.b64 %0, {%1, %2};" : "=l"(r) : "f"(lo), "f"(hi));
    return r;
}
__device__ __forceinline__ void unpack2(unsigned long long v, float& lo, float& hi) {
    asm("mov.b64 {%0, %1}, %2;" : "=f"(lo), "=f"(hi) : "l"(v));
}
__device__ __forceinline__ void ffma2(unsigned long long& d, unsigned long long a,
                                      unsigned long long b) {
    asm("fma.rn.f32x2 %0, %1, %2, %0;" : "+l"(d) : "l"(a), "l"(b));
}

__device__ __forceinline__ float4 bnrelu4(float4 v, float4 sc, float4 sh) {
    float4 r;
    r.x = fmaxf(fmaf(sc.x, v.x, sh.x), 0.f);
    r.y = fmaxf(fmaf(sc.y, v.y, sh.y), 0.f);
    r.z = fmaxf(fmaf(sc.z, v.z, sh.z), 0.f);
    r.w = fmaxf(fmaf(sc.w, v.w, sh.w), 0.f);
    return r;
}

// load 4 consecutive fp16 as float4 (8-byte aligned)
__device__ __forceinline__ float4 ld_half4(const __half* p) {
    uint2 r = *(const uint2*)p;
    float2 a = __half22float2(*(__half2*)&r.x);
    float2 b = __half22float2(*(__half2*)&r.y);
    return make_float4(a.x, a.y, b.x, b.y);
}
// store float4 as 4 fp16 (8-byte aligned)
__device__ __forceinline__ void st_half4(__half* p, float4 v) {
    __half2 a = __floats2half2_rn(v.x, v.y);
    __half2 b = __floats2half2_rn(v.z, v.w);
    uint2 r;
    r.x = *(unsigned*)&a;
    r.y = *(unsigned*)&b;
    *(uint2*)p = r;
}

// ---------------- x -> fp16 ----------------
__global__ void k_xcast(const float* __restrict__ x) {
    int i = blockIdx.x * blockDim.x + threadIdx.x;   // pair index
    if (i < CN * CF / 2) {
        float2 v = ((const float2*)x)[i];
        ((__half2*)g_x16)[i] = __floats2half2_rn(v.x, v.y);
    }
}

// ---------------- CSR build (edge_index is int32) ----------------
__global__ void k_deg(const int* __restrict__ ei) {
    int e = blockIdx.x * blockDim.x + threadIdx.x;
    if (e < CE) atomicAdd(&g_deg[ei[CE + e]], 1);
}

__global__ void k_scan1() {     // block scan; also dinv + cursor zero
    __shared__ int s[1024];
    int tid = threadIdx.x;
    int i = blockIdx.x * 1024 + tid;
    int v = (i < CN) ? g_deg[i] : 0;
    if (i < CN) {
        g_dinv[i] = rsqrtf((float)(v + 1));   // +1 self loop
        g_cursor[i] = 0;
    }
    s[tid] = v;
    __syncthreads();
    for (int off = 1; off < 1024; off <<= 1) {
        int t = (tid >= off) ? s[tid - off] : 0;
        __syncthreads();
        s[tid] += t;
        __syncthreads();
    }
    if (i < CN) g_rowptr[i] = s[tid] - v;   // exclusive within block
    if (tid == 1023) g_bsums[blockIdx.x] = s[1023];
}

// merged scan2+scan3 (256-thread blocks) + sums zero
__global__ void k_scanfix() {
    __shared__ int s[256];
    __shared__ int sx[256];
    int tid = threadIdx.x;
    int v = (tid < NB_SCAN) ? g_bsums[tid] : 0;
    s[tid] = v;
    __syncthreads();
    for (int off = 1; off < 128; off <<= 1) {
        int t = (tid >= off) ? s[tid - off] : 0;
        __syncthreads();
        s[tid] += t;
        __syncthreads();
    }
    sx[tid] = s[tid] - v;   // exclusive
    __syncthreads();
    int i = blockIdx.x * blockDim.x + tid;
    if (i < CN) g_rowptr[i] += sx[i >> 10];
    if (blockIdx.x == 0)
        for (int j = tid; j < 6 * CH; j += blockDim.x) g_sums[j] = 0.f;
}

__global__ void k_scatter(const int* __restrict__ ei) {
    int e = blockIdx.x * blockDim.x + threadIdx.x;
    if (e < CE) {
        int d = ei[CE + e];
        int p = atomicAdd(&g_cursor[d], 1);
        g_col[g_rowptr[d] + p] = ei[e];
    }
}

// ---------------- aggregation: out = A_norm @ x (x in fp16) ----------------
__global__ void __launch_bounds__(256) k_agg32() {
    int warp = (blockIdx.x * blockDim.x + threadIdx.x) >> 5;
    if (warp >= CN) return;
    int lane = threadIdx.x & 31;
    float dv = g_dinv[warp];
    float acc = dv * dv * __half2float(g_x16[(size_t)warp * CF + lane]);  // self loop
    int e = g_rowptr[warp];
    int e1 = e + g_deg[warp];
    for (; e + 3 < e1; e += 4) {
        int s0 = g_col[e], s1 = g_col[e + 1], s2 = g_col[e + 2], s3 = g_col[e + 3];
        float w0 = g_dinv[s0] * dv, w1 = g_dinv[s1] * dv;
        float w2 = g_dinv[s2] * dv, w3 = g_dinv[s3] * dv;
        acc = fmaf(w0, __half2float(g_x16[(size_t)s0 * CF + lane]), acc);
        acc = fmaf(w1, __half2float(g_x16[(size_t)s1 * CF + lane]), acc);
        acc = fmaf(w2, __half2float(g_x16[(size_t)s2 * CF + lane]), acc);
        acc = fmaf(w3, __half2float(g_x16[(size_t)s3 * CF + lane]), acc);
    }
    for (; e < e1; e++) {
        int s = g_col[e];
        acc = fmaf(g_dinv[s] * dv, __half2float(g_x16[(size_t)s * CF + lane]), acc);
    }
    g_bufA16[(size_t)warp * CF + lane] = __float2half_rn(acc);
}

// Layers 1/2: fp16 gather; BN params computed in-block from sums; 8-edge unroll.
__global__ void __launch_bounds__(256) k_agg128(const __half* __restrict__ xin,
                                                const float* __restrict__ sums,
                                                const float* __restrict__ gamma,
                                                const float* __restrict__ beta,
                                                __half* __restrict__ out) {
    __shared__ float4 s_sc4[32], s_sh4[32];
    int tid = threadIdx.x;
    if (tid < 128) {
        float mean = sums[tid] * (1.f / CN);
        float var = sums[128 + tid] * (1.f / CN) - mean * mean;
        float sc = gamma[tid] * rsqrtf(var + 1e-5f);
        ((float*)s_sc4)[tid] = sc;
        ((float*)s_sh4)[tid] = fmaf(-mean, sc, beta[tid]);
    }
    __syncthreads();

    int warp = (blockIdx.x * blockDim.x + tid) >> 5;
    if (warp >= CN) return;
    int lane = tid & 31;
    float4 sc = s_sc4[lane];
    float4 sh = s_sh4[lane];
    float dv = g_dinv[warp];
    float4 v = ld_half4(xin + (size_t)warp * CH + lane * 4);
    v = bnrelu4(v, sc, sh);
    float dv2 = dv * dv;
    float4 acc = make_float4(dv2 * v.x, dv2 * v.y, dv2 * v.z, dv2 * v.w);
    int e = g_rowptr[warp];
    int e1 = e + g_deg[warp];
    for (; e + 7 < e1; e += 8) {
        int s0 = g_col[e],     s1 = g_col[e + 1], s2 = g_col[e + 2], s3 = g_col[e + 3];
        int s4 = g_col[e + 4], s5 = g_col[e + 5], s6 = g_col[e + 6], s7 = g_col[e + 7];
        float w0 = g_dinv[s0] * dv, w1 = g_dinv[s1] * dv;
        float w2 = g_dinv[s2] * dv, w3 = g_dinv[s3] * dv;
        float w4 = g_dinv[s4] * dv, w5 = g_dinv[s5] * dv;
        float w6 = g_dinv[s6] * dv, w7 = g_dinv[s7] * dv;
        float4 u0 = ld_half4(xin + (size_t)s0 * CH + lane * 4);
        float4 u1 = ld_half4(xin + (size_t)s1 * CH + lane * 4);
        float4 u2 = ld_half4(xin + (size_t)s2 * CH + lane * 4);
        float4 u3 = ld_half4(xin + (size_t)s3 * CH + lane * 4);
        float4 u4 = ld_half4(xin + (size_t)s4 * CH + lane * 4);
        float4 u5 = ld_half4(xin + (size_t)s5 * CH + lane * 4);
        float4 u6 = ld_half4(xin + (size_t)s6 * CH + lane * 4);
        float4 u7 = ld_half4(xin + (size_t)s7 * CH + lane * 4);
        u0 = bnrelu4(u0, sc, sh); u1 = bnrelu4(u1, sc, sh);
        u2 = bnrelu4(u2, sc, sh); u3 = bnrelu4(u3, sc, sh);
        u4 = bnrelu4(u4, sc, sh); u5 = bnrelu4(u5, sc, sh);
        u6 = bnrelu4(u6, sc, sh); u7 = bnrelu4(u7, sc, sh);
        acc.x = fmaf(w0, u0.x, acc.x); acc.y = fmaf(w0, u0.y, acc.y);
        acc.z = fmaf(w0, u0.z, acc.z); acc.w = fmaf(w0, u0.w, acc.w);
        acc.x = fmaf(w1, u1.x, acc.x); acc.y = fmaf(w1, u1.y, acc.y);
        acc.z = fmaf(w1, u1.z, acc.z); acc.w = fmaf(w1, u1.w, acc.w);
        acc.x = fmaf(w2, u2.x, acc.x); acc.y = fmaf(w2, u2.y, acc.y);
        acc.z = fmaf(w2, u2.z, acc.z); acc.w = fmaf(w2, u2.w, acc.w);
        acc.x = fmaf(w3, u3.x, acc.x); acc.y = fmaf(w3, u3.y, acc.y);
        acc.z = fmaf(w3, u3.z, acc.z); acc.w = fmaf(w3, u3.w, acc.w);
        acc.x = fmaf(w4, u4.x, acc.x); acc.y = fmaf(w4, u4.y, acc.y);
        acc.z = fmaf(w4, u4.z, acc.z); acc.w = fmaf(w4, u4.w, acc.w);
        acc.x = fmaf(w5, u5.x, acc.x); acc.y = fmaf(w5, u5.y, acc.y);
        acc.z = fmaf(w5, u5.z, acc.z); acc.w = fmaf(w5, u5.w, acc.w);
        acc.x = fmaf(w6, u6.x, acc.x); acc.y = fmaf(w6, u6.y, acc.y);
        acc.z = fmaf(w6, u6.z, acc.z); acc.w = fmaf(w6, u6.w, acc.w);
        acc.x = fmaf(w7, u7.x, acc.x); acc.y = fmaf(w7, u7.y, acc.y);
        acc.z = fmaf(w7, u7.z, acc.z); acc.w = fmaf(w7, u7.w, acc.w);
    }
    for (; e + 3 < e1; e += 4) {
        int s0 = g_col[e], s1 = g_col[e + 1], s2 = g_col[e + 2], s3 = g_col[e + 3];
        float w0 = g_dinv[s0] * dv, w1 = g_dinv[s1] * dv;
        float w2 = g_dinv[s2] * dv, w3 = g_dinv[s3] * dv;
        float4 u0 = ld_half4(xin + (size_t)s0 * CH + lane * 4);
        float4 u1 = ld_half4(xin + (size_t)s1 * CH + lane * 4);
        float4 u2 = ld_half4(xin + (size_t)s2 * CH + lane * 4);
        float4 u3 = ld_half4(xin + (size_t)s3 * CH + lane * 4);
        u0 = bnrelu4(u0, sc, sh); u1 = bnrelu4(u1, sc, sh);
        u2 = bnrelu4(u2, sc, sh); u3 = bnrelu4(u3, sc, sh);
        acc.x = fmaf(w0, u0.x, acc.x); acc.y = fmaf(w0, u0.y, acc.y);
        acc.z = fmaf(w0, u0.z, acc.z); acc.w = fmaf(w0, u0.w, acc.w);
        acc.x = fmaf(w1, u1.x, acc.x); acc.y = fmaf(w1, u1.y, acc.y);
        acc.z = fmaf(w1, u1.z, acc.z); acc.w = fmaf(w1, u1.w, acc.w);
        acc.x = fmaf(w2, u2.x, acc.x); acc.y = fmaf(w2, u2.y, acc.y);
        acc.z = fmaf(w2, u2.z, acc.z); acc.w = fmaf(w2, u2.w, acc.w);
        acc.x = fmaf(w3, u3.x, acc.x); acc.y = fmaf(w3, u3.y, acc.y);
        acc.z = fmaf(w3, u3.z, acc.z); acc.w = fmaf(w3, u3.w, acc.w);
    }
    for (; e < e1; e++) {
        int s = g_col[e];
        float w = g_dinv[s] * dv;
        float4 u = ld_half4(xin + (size_t)s * CH + lane * 4);
        u = bnrelu4(u, sc, sh);
        acc.x = fmaf(w, u.x, acc.x); acc.y = fmaf(w, u.y, acc.y);
        acc.z = fmaf(w, u.z, acc.z); acc.w = fmaf(w, u.w, acc.w);
    }
    st_half4(out + (size_t)warp * CH + lane * 4, acc);
}

// ---------------- GEMM: h = A @ W + bias (fp32 compute), fp16 A/out, fp32 stats -
template <int K>
__global__ void __launch_bounds__(256, 2) k_gemm(const __half* __restrict__ A,
                                                 const float* __restrict__ W,
                                                 const float* __restrict__ bias,
                                                 __half* __restrict__ out,
                                                 float* __restrict__ sums) {
    extern __shared__ float sm[];
    float* Ws = sm;               // [K][128]
    float* As = sm + K * 128;     // [32][ASTR] k-major chunk
    int tid = threadIdx.x;
    int tx = tid & 15;
    int ty = tid >> 4;
    int row0 = blockIdx.x * 128;

    for (int i = tid; i < K * 128; i += 256) Ws[i] = W[i];

    unsigned long long acc[8][4];   // 8 rows x 4 col-pairs
#pragma unroll
    for (int i = 0; i < 8; i++)
#pragma unroll
        for (int j = 0; j < 4; j++) acc[i][j] = 0ull;

    for (int kc = 0; kc < K; kc += 32) {
        __syncthreads();
        for (int i = tid; i < 128 * 32; i += 256) {
            int r = i >> 5, k = i & 31;
            int gr = row0 + r;
            float v = (gr < CN) ? __half2float(A[(size_t)gr * K + kc + k]) : 0.f;
            As[k * ASTR + r] = v;
        }
        __syncthreads();
#pragma unroll
        for (int k = 0; k < 32; k++) {
            float4 a0 = *(const float4*)&As[k * ASTR + ty * 8];
            float4 a1 = *(const float4*)&As[k * ASTR + ty * 8 + 4];
            const ulonglong2* Brow = (const ulonglong2*)&Ws[(kc + k) * 128 + tx * 8];
            ulonglong2 q0 = Brow[0];
            ulonglong2 q1 = Brow[1];
            unsigned long long bp[4] = {q0.x, q0.y, q1.x, q1.y};
            float av[8] = {a0.x, a0.y, a0.z, a0.w, a1.x, a1.y, a1.z, a1.w};
#pragma unroll
            for (int i = 0; i < 8; i++) {
                unsigned long long ap = pack2(av[i], av[i]);
#pragma unroll
                for (int j = 0; j < 4; j++) ffma2(acc[i][j], ap, bp[j]);
            }
        }
    }

    // epilogue: + bias, fp32 stats, fp16 store
    float4 bj0 = *(const float4*)&bias[tx * 8];
    float4 bj1 = *(const float4*)&bias[tx * 8 + 4];
    float bj[8] = {bj0.x, bj0.y, bj0.z, bj0.w, bj1.x, bj1.y, bj1.z, bj1.w};
    float csum[8], csq[8];
#pragma unroll
    for (int j = 0; j < 8; j++) { csum[j] = 0.f; csq[j] = 0.f; }
#pragma unroll
    for (int i = 0; i < 8; i++) {
        int r = row0 + ty * 8 + i;
        if (r < CN) {
            float v[8];
#pragma unroll
            for (int j = 0; j < 4; j++) unpack2(acc[i][j], v[2 * j], v[2 * j + 1]);
#pragma unroll
            for (int j = 0; j < 8; j++) {
                v[j] += bj[j];
                csum[j] += v[j];
                csq[j] += v[j] * v[j];
            }
            __half2 h01 = __floats2half2_rn(v[0], v[1]);
            __half2 h23 = __floats2half2_rn(v[2], v[3]);
            __half2 h45 = __floats2half2_rn(v[4], v[5]);
            __half2 h67 = __floats2half2_rn(v[6], v[7]);
            uint4 pk;
            pk.x = *(unsigned*)&h01;
            pk.y = *(unsigned*)&h23;
            pk.z = *(unsigned*)&h45;
            pk.w = *(unsigned*)&h67;
            *(uint4*)(out + (size_t)r * 128 + tx * 8) = pk;
        }
    }
    // block reduce stats via smem, one atomic per column per block
    __syncthreads();
    float* red = sm;  // 16*128 floats
#pragma unroll
    for (int j = 0; j < 8; j++) red[ty * 128 + tx * 8 + j] = csum[j];
    __syncthreads();
    if (tid < 128) {
        float t = 0.f;
#pragma unroll
        for (int q = 0; q < 16; q++) t += red[q * 128 + tid];
        atomicAdd(&sums[tid], t);
    }
    __syncthreads();
#pragma unroll
    for (int j = 0; j < 8; j++) red[ty * 128 + tx * 8 + j] = csq[j];
    __syncthreads();
    if (tid < 128) {
        float t = 0.f;
#pragma unroll
        for (int q = 0; q < 16; q++) t += red[q * 128 + tid];
        atomicAdd(&sums[128 + tid], t);
    }
}

// ---------------- fused pooling + MLP head (batch sorted; BN from sums) --------
__global__ void __launch_bounds__(128) k_poolhead(const int* __restrict__ batch,
                                                  const float* __restrict__ sums,
                                                  const float* __restrict__ gamma,
                                                  const float* __restrict__ beta,
                                                  const float* __restrict__ Wh1,
                                                  const float* __restrict__ bh1,
                                                  const float* __restrict__ Wh2,
                                                  const float* __restrict__ bh2,
                                                  float* __restrict__ out) {
    __shared__ float row[128];
    __shared__ float red[64];
    int g = blockIdx.x;
    int t = threadIdx.x;  // 128 threads

    float mean = sums[t] * (1.f / CN);
    float var = sums[128 + t] * (1.f / CN) - mean * mean;
    float sc = gamma[t] * rsqrtf(var + 1e-5f);
    float sh = fmaf(-mean, sc, beta[t]);

    int lo = 0, hi = CN;
    while (lo < hi) { int m = (lo + hi) >> 1; if (batch[m] < g) lo = m + 1; else hi = m; }
    int start = lo;
    hi = CN;
    while (lo < hi) { int m = (lo + hi) >> 1; if (batch[m] < g + 1) lo = m + 1; else hi = m; }
    int end = lo;

    float acc = 0.f;
    for (int i = start; i < end; i++)
        acc += fmaxf(fmaf(sc, __half2float(g_bufB16[(size_t)i * CH + t]), sh), 0.f);
    float inv = 1.f / fmaxf((float)(end - start), 1.f);
    row[t] = acc * inv;
    __syncthreads();

    if (t < 64) {
        float a = bh1[t];
#pragma unroll 8
        for (int f = 0; f < 128; f++) a = fmaf(row[f], Wh1[f * 64 + t], a);
        a = fmaxf(a, 0.f);
        red[t] = a * Wh2[t];
    }
    __syncthreads();
    if (t < 32) {
        float v = red[t] + red[t + 32];
#pragma unroll
        for (int off = 16; off > 0; off >>= 1)
            v += __shfl_down_sync(0xffffffffu, v, off);
        if (t == 0) out[g] = v + bh2[0];
    }
}

// ---------------- launch ----------------
extern "C" void kernel_launch(void* const* d_in, const int* in_sizes, int n_in,
                              void* d_out, int out_size) {
    const float* x  = (const float*)d_in[0];
    const int* ei   = (const int*)d_in[1];     // int32 (JAX x64 disabled)
    const int* batch= (const int*)d_in[2];     // int32
    const float* W0 = (const float*)d_in[3];
    const float* b0 = (const float*)d_in[4];
    const float* g0 = (const float*)d_in[5];
    const float* be0= (const float*)d_in[6];
    const float* W1 = (const float*)d_in[7];
    const float* b1 = (const float*)d_in[8];
    const float* g1 = (const float*)d_in[9];
    const float* be1= (const float*)d_in[10];
    const float* W2 = (const float*)d_in[11];
    const float* b2 = (const float*)d_in[12];
    const float* g2 = (const float*)d_in[13];
    const float* be2= (const float*)d_in[14];
    const float* Wh1= (const float*)d_in[15];
    const float* bh1= (const float*)d_in[16];
    const float* Wh2= (const float*)d_in[17];
    const float* bh2= (const float*)d_in[18];
    float* out = (float*)d_out;

    void* p;
    cudaGetSymbolAddress(&p, g_deg);     int*    degp   = (int*)p;
    cudaGetSymbolAddress(&p, g_bufA16);  __half* bufA16 = (__half*)p;
    cudaGetSymbolAddress(&p, g_bufB16);  __half* bufB16 = (__half*)p;
    cudaGetSymbolAddress(&p, g_sums);    float*  sums   = (float*)p;

    const int SM128 = (128 * 128 + 32 * ASTR) * 4;  // 82432 B
    const int SM32  = (32 * 128 + 32 * ASTR) * 4;   // 33280 B
    cudaFuncSetAttribute(k_gemm<128>, cudaFuncAttributeMaxDynamicSharedMemorySize, SM128);
    cudaFuncSetAttribute(k_gemm<32>,  cudaFuncAttributeMaxDynamicSharedMemorySize, SM32);

    const int gemmBlocks = (CN + 127) / 128;   // 782
    const int aggBlocks = (CN + 7) / 8;        // 12500

    cudaMemsetAsync(degp, 0, CN * sizeof(int));
    k_xcast<<<(CN * CF / 2 + 255) / 256, 256>>>(x);
    k_deg<<<(CE + 255) / 256, 256>>>(ei);
    k_scan1<<<NB_SCAN, 1024>>>();
    k_scanfix<<<(CN + 255) / 256, 256>>>();
    k_scatter<<<(CE + 255) / 256, 256>>>(ei);

    // Layer 0
    k_agg32<<<aggBlocks, 256>>>();
    k_gemm<32><<<gemmBlocks, 256, SM32>>>(bufA16, W0, b0, bufB16, sums);

    // Layer 1 (BN params for layer 0 computed inside agg128 from sums)
    k_agg128<<<aggBlocks, 256>>>(bufB16, sums, g0, be0, bufA16);
    k_gemm<128><<<gemmBlocks, 256, SM128>>>(bufA16, W1, b1, bufB16, sums + 256);

    // Layer 2
    k_agg128<<<aggBlocks, 256>>>(bufB16, sums + 256, g1, be1, bufA16);
    k_gemm<128><<<gemmBlocks, 256, SM128>>>(bufA16, W2, b2, bufB16, sums + 512);

    // Fused pool + head (BN params from sums inside)
    k_poolhead<<<CG, 128>>>(batch, sums + 512, g2, be2, Wh1, bh1, Wh2, bh2, out);
}